// round 3
// baseline (speedup 1.0000x reference)
#include <cuda_runtime.h>
#include <math.h>

#define IMW 1024
#define IMH 1024
#define NB 4
#define NQ 262144      // queries per batch (2^18)
#define DCAP 46        // distances >= 46 all map to weight 1.0

// Scratch: uint8 distance fields (device globals — no allocation allowed)
__device__ unsigned char g_h[(size_t)NB * IMH * IMW];  // per-row nearest-zero distance, capped
__device__ unsigned char g_d[(size_t)NB * IMH * IMW];  // capped Chebyshev distance to nearest zero

// ---------------------------------------------------------------------------
// Kernel 1: per-row 1D distance to nearest zero, capped at DCAP.
// One block = one row (1024 threads). Early-exit outward scan in shared mem.
// ---------------------------------------------------------------------------
__global__ void row_dist_kernel(const float* __restrict__ mask) {
    __shared__ unsigned char zf[IMW];
    const int row = blockIdx.x;                      // 0 .. NB*IMH-1
    const int t = threadIdx.x;
    const float v = mask[(size_t)row * IMW + t];
    zf[t] = (v == 0.0f) ? 1 : 0;
    __syncthreads();

    int h;
    if (zf[t]) {
        h = 0;
    } else {
        h = DCAP;
        #pragma unroll 1
        for (int r = 1; r <= DCAP - 1; ++r) {
            const int l = t - r;
            const int rr = t + r;
            bool hit = false;
            if (l >= 0 && zf[l]) hit = true;
            if (rr < IMW && zf[rr]) hit = true;
            if (hit) { h = r; break; }
        }
    }
    g_h[(size_t)row * IMW + t] = (unsigned char)h;
}

// ---------------------------------------------------------------------------
// Kernel 2: Chebyshev DT combine: d(x,y) = min_r max(r, min(h[y-r], h[y+r])),
// capped at DCAP, early exit once r >= current best.
// One thread per pixel; x is the fast dimension -> coalesced column reads.
// ---------------------------------------------------------------------------
__global__ void col_dist_kernel() {
    const int i = blockIdx.x * blockDim.x + threadIdx.x;    // 0 .. NB*IMH*IMW-1
    const int x = i & (IMW - 1);
    const int y = (i >> 10) & (IMH - 1);
    const int b = i >> 20;
    const unsigned char* hp = g_h + (size_t)b * IMH * IMW;

    int best = hp[y * IMW + x];                              // r = 0 term
    #pragma unroll 1
    for (int r = 1; r < best; ++r) {
        const int yu = y - r;
        const int yd = y + r;
        int cand = DCAP;
        if (yu >= 0)  cand = hp[yu * IMW + x];
        if (yd < IMH) { const int c2 = hp[yd * IMW + x]; cand = min(cand, c2); }
        const int v = max(r, cand);
        if (v < best) best = v;
    }
    g_d[i] = (unsigned char)best;
}

// Weight as a function of capped Chebyshev distance:
//   d == 0            -> 0
//   1 <= d            -> 0.1 + 0.06 * min(15, floor((d-1)/3))   (d>=46 -> 1.0)
__device__ __forceinline__ float weight_from_d(int d) {
    if (d == 0) return 0.0f;
    int k = (d - 1) / 3;
    if (k > 15) k = 15;
    return 0.1f + 0.06f * (float)k;
}

// ---------------------------------------------------------------------------
// Kernel 3: fused bilinear sampling + psdf weighting + occupancy fusion.
// One thread per query point. Gathers are served out of L2 (36 MB resident).
// ---------------------------------------------------------------------------
__global__ void fuse_kernel(const float* __restrict__ face_depth,
                            const float* __restrict__ edge_mask,
                            const float* __restrict__ xy,
                            const float* __restrict__ z,
                            const float* __restrict__ occ_body,
                            const float* __restrict__ occ_face,
                            float* __restrict__ out) {
    const int i = blockIdx.x * blockDim.x + threadIdx.x;
    if (i >= NB * NQ) return;
    const int b = i >> 18;            // i / NQ
    const int n = i & (NQ - 1);       // i % NQ

    const float px = xy[(size_t)b * 2 * NQ + n];
    const float py = xy[(size_t)b * 2 * NQ + NQ + n];

    const float gx = (px + 1.0f) * 0.5f * (float)(IMW - 1);
    const float gy = (py + 1.0f) * 0.5f * (float)(IMH - 1);
    const float x0f = floorf(gx);
    const float y0f = floorf(gy);
    const float wx = gx - x0f;
    const float wy = gy - y0f;

    const int x0 = (int)fminf(fmaxf(x0f,        0.0f), (float)(IMW - 1));
    const int x1 = (int)fminf(fmaxf(x0f + 1.0f, 0.0f), (float)(IMW - 1));
    const int y0 = (int)fminf(fmaxf(y0f,        0.0f), (float)(IMH - 1));
    const int y1 = (int)fminf(fmaxf(y0f + 1.0f, 0.0f), (float)(IMH - 1));

    const size_t base = (size_t)b * IMH * IMW;
    const size_t i00 = base + (size_t)y0 * IMW + x0;
    const size_t i10 = base + (size_t)y0 * IMW + x1;
    const size_t i01 = base + (size_t)y1 * IMW + x0;
    const size_t i11 = base + (size_t)y1 * IMW + x1;

    const float w00 = (1.0f - wx) * (1.0f - wy);
    const float w10 = wx * (1.0f - wy);
    const float w01 = (1.0f - wx) * wy;
    const float w11 = wx * wy;

    const float edge = __ldg(edge_mask + i00) * w00 + __ldg(edge_mask + i10) * w10
                     + __ldg(edge_mask + i01) * w01 + __ldg(edge_mask + i11) * w11;

    const float ob = occ_body[i];
    float res = ob;
    if (edge > 0.01f) {
        const float dq = __ldg(face_depth + i00) * w00 + __ldg(face_depth + i10) * w10
                       + __ldg(face_depth + i01) * w01 + __ldg(face_depth + i11) * w11;
        const float lab = weight_from_d((int)g_d[i00]) * w00
                        + weight_from_d((int)g_d[i10]) * w10
                        + weight_from_d((int)g_d[i01]) * w01
                        + weight_from_d((int)g_d[i11]) * w11;
        const float psdf = z[i] - dq;
        const float w = expf(-psdf * psdf * 1000.0f) * lab;
        res = w * occ_face[i] + (1.0f - w) * ob;
    }
    out[i] = res;
}

// ---------------------------------------------------------------------------
extern "C" void kernel_launch(void* const* d_in, const int* in_sizes, int n_in,
                              void* d_out, int out_size) {
    const float* mask       = (const float*)d_in[0];
    const float* face_depth = (const float*)d_in[1];
    const float* edge_mask  = (const float*)d_in[2];
    const float* xy         = (const float*)d_in[3];
    const float* z          = (const float*)d_in[4];
    const float* occ_body   = (const float*)d_in[5];
    const float* occ_face   = (const float*)d_in[6];
    float* out = (float*)d_out;

    (void)in_sizes; (void)n_in; (void)out_size; (void)z;

    // 1) per-row nearest-zero distance
    row_dist_kernel<<<NB * IMH, IMW>>>(mask);
    // 2) Chebyshev DT combine (column pass)
    col_dist_kernel<<<(NB * IMH * IMW) / 256, 256>>>();
    // 3) fused sampling + fusion
    fuse_kernel<<<(NB * NQ + 255) / 256, 256>>>(face_depth, edge_mask, xy, z,
                                                occ_body, occ_face, out);
}

// round 5
// speedup vs baseline: 1.1164x; 1.1164x over previous
#include <cuda_runtime.h>
#include <math.h>

#define IMW 1024
#define IMH 1024
#define NB 4
#define NQ 262144      // queries per batch (2^18)
#define DCAP 46        // distances >= 46 all map to weight 1.0

// Scratch (device globals — no allocation allowed)
__device__ unsigned char g_h[(size_t)NB * IMH * IMW];   // per-row nearest-zero distance, capped
__device__ uint2         g_p[(size_t)NB * IMH * IMW];   // packed {depth f32, edge u8 | wcode<<8}

// ---------------------------------------------------------------------------
// Kernel 1: per-row 1D distance to nearest zero, capped at DCAP.
// One block = one row (1024 threads). Zero flags -> 1024-bit bitmap via
// ballot; nearest-zero via 64-bit windows + ffsll. No loops, no divergence.
// ---------------------------------------------------------------------------
__global__ void row_dist_kernel(const float* __restrict__ mask) {
    __shared__ unsigned int zw[32];
    const int row = blockIdx.x;                      // 0 .. NB*IMH-1
    const int t = threadIdx.x;
    const float v = mask[(size_t)row * IMW + t];
    const bool isz = (v == 0.0f);
    const unsigned int bal = __ballot_sync(0xFFFFFFFFu, isz);
    if ((t & 31) == 0) zw[t >> 5] = bal;
    __syncthreads();

    const int word = t >> 5;
    const int bitpos = t & 31;

    // Right window: bit k = zeroflag(t + k), k in [0, 63]
    const unsigned int w0 = zw[word];
    const unsigned int w1 = (word + 1 < 32) ? zw[word + 1] : 0u;
    const unsigned int w2 = (word + 2 < 32) ? zw[word + 2] : 0u;
    unsigned long long R = ((unsigned long long)w0 | ((unsigned long long)w1 << 32)) >> bitpos;
    if (bitpos) R |= ((unsigned long long)w2) << (64 - bitpos);

    // Left window: bit k = zeroflag(t - k), k in [0, 63]
    const unsigned int la  = __brev(w0);
    const unsigned int lb  = (word >= 1) ? __brev(zw[word - 1]) : 0u;
    const unsigned int lc  = (word >= 2) ? __brev(zw[word - 2]) : 0u;
    unsigned long long L = ((unsigned long long)la | ((unsigned long long)lb << 32)) >> (31 - bitpos);
    if (bitpos != 31) L |= ((unsigned long long)lc) << (33 + bitpos);

    const int rd = R ? (__ffsll((long long)R) - 1) : 64;
    const int ld = L ? (__ffsll((long long)L) - 1) : 64;
    int h = min(rd, ld);
    h = min(h, DCAP);
    g_h[(size_t)row * IMW + t] = (unsigned char)h;
}

// ---------------------------------------------------------------------------
// Kernel 2: Chebyshev DT column combine + pack per-pixel fusion record.
// d(x,y) = min_r max(r, min(h[y-r], h[y+r])), early exit once r >= best.
// Emits {depth f32, edge u8, weight-code u8} as uint2 (8B) per pixel so the
// sampler needs only ONE gather per bilinear corner.
// ---------------------------------------------------------------------------
__global__ void col_pack_kernel(const float* __restrict__ face_depth,
                                const float* __restrict__ edge_mask) {
    const int i = blockIdx.x * blockDim.x + threadIdx.x;    // 0 .. NB*IMH*IMW-1
    const int x = i & (IMW - 1);
    const int y = (i >> 10) & (IMH - 1);
    const int b = i >> 20;
    const unsigned char* hp = g_h + (size_t)b * IMH * IMW;

    int best = hp[y * IMW + x];                              // r = 0 term
    #pragma unroll 1
    for (int r = 1; r < best; ++r) {
        const int yu = y - r;
        const int yd = y + r;
        int cand = DCAP;
        if (yu >= 0)  cand = hp[yu * IMW + x];
        if (yd < IMH) { const int c2 = hp[yd * IMW + x]; cand = min(cand, c2); }
        const int v = max(r, cand);
        if (v < best) best = v;
    }
    // weight code: 0 -> weight 0 (d==0); else 1 + min(15, (d-1)/3)
    int code = 0;
    if (best > 0) {
        int k = (best - 1) / 3;
        if (k > 15) k = 15;
        code = 1 + k;
    }
    const int e = (edge_mask[i] != 0.0f) ? 1 : 0;
    uint2 p;
    p.x = __float_as_uint(face_depth[i]);
    p.y = (unsigned int)e | ((unsigned int)code << 8);
    g_p[i] = p;
}

// ---------------------------------------------------------------------------
// Kernel 3: fused bilinear sampling + psdf weighting + occupancy fusion.
// One thread per query; 4 x 8B gathers (L2-resident, 32MB packed image).
// Branch-free: edge_b is a multiplier, exactly matching the reference algebra.
// ---------------------------------------------------------------------------
__global__ void fuse_kernel(const float* __restrict__ xy,
                            const float* __restrict__ z,
                            const float* __restrict__ occ_body,
                            const float* __restrict__ occ_face,
                            float* __restrict__ out) {
    const int i = blockIdx.x * blockDim.x + threadIdx.x;
    if (i >= NB * NQ) return;
    const int b = i >> 18;            // i / NQ
    const int n = i & (NQ - 1);       // i % NQ

    const float px = xy[(size_t)b * 2 * NQ + n];
    const float py = xy[(size_t)b * 2 * NQ + NQ + n];

    const float gx = (px + 1.0f) * 0.5f * (float)(IMW - 1);
    const float gy = (py + 1.0f) * 0.5f * (float)(IMH - 1);
    const float x0f = floorf(gx);
    const float y0f = floorf(gy);
    const float wx = gx - x0f;
    const float wy = gy - y0f;

    const int x0 = (int)fminf(fmaxf(x0f,        0.0f), (float)(IMW - 1));
    const int x1 = (int)fminf(fmaxf(x0f + 1.0f, 0.0f), (float)(IMW - 1));
    const int y0 = (int)fminf(fmaxf(y0f,        0.0f), (float)(IMH - 1));
    const int y1 = (int)fminf(fmaxf(y0f + 1.0f, 0.0f), (float)(IMH - 1));

    const size_t base = (size_t)b * IMH * IMW;
    const uint2 u00 = __ldg(&g_p[base + (size_t)y0 * IMW + x0]);
    const uint2 u10 = __ldg(&g_p[base + (size_t)y0 * IMW + x1]);
    const uint2 u01 = __ldg(&g_p[base + (size_t)y1 * IMW + x0]);
    const uint2 u11 = __ldg(&g_p[base + (size_t)y1 * IMW + x1]);

    const float w00 = (1.0f - wx) * (1.0f - wy);
    const float w10 = wx * (1.0f - wy);
    const float w01 = (1.0f - wx) * wy;
    const float w11 = wx * wy;

    // edge bilinear (values are exact 0.0/1.0 -> identical to reference fp32)
    const float edge = (float)(u00.y & 0xFFu) * w00 + (float)(u10.y & 0xFFu) * w10
                     + (float)(u01.y & 0xFFu) * w01 + (float)(u11.y & 0xFFu) * w11;

    // depth bilinear
    const float dq = __uint_as_float(u00.x) * w00 + __uint_as_float(u10.x) * w10
                   + __uint_as_float(u01.x) * w01 + __uint_as_float(u11.x) * w11;

    // erosion-weight bilinear (reconstruct fp32 weight from code)
    const int c00 = (int)(u00.y >> 8), c10 = (int)(u10.y >> 8);
    const int c01 = (int)(u01.y >> 8), c11 = (int)(u11.y >> 8);
    const float v00 = c00 ? (0.1f + 0.06f * (float)(c00 - 1)) : 0.0f;
    const float v10 = c10 ? (0.1f + 0.06f * (float)(c10 - 1)) : 0.0f;
    const float v01 = c01 ? (0.1f + 0.06f * (float)(c01 - 1)) : 0.0f;
    const float v11 = c11 ? (0.1f + 0.06f * (float)(c11 - 1)) : 0.0f;
    const float lab = v00 * w00 + v10 * w10 + v01 * w01 + v11 * w11;

    const float eb = (edge > 0.01f) ? 1.0f : 0.0f;
    const float psdf = z[i] - dq * eb;
    const float w = expf(-psdf * psdf * 1000.0f) * lab * eb;

    const float ob = occ_body[i];
    out[i] = w * occ_face[i] + (1.0f - w) * ob;
}

// ---------------------------------------------------------------------------
extern "C" void kernel_launch(void* const* d_in, const int* in_sizes, int n_in,
                              void* d_out, int out_size) {
    const float* mask       = (const float*)d_in[0];
    const float* face_depth = (const float*)d_in[1];
    const float* edge_mask  = (const float*)d_in[2];
    const float* xy         = (const float*)d_in[3];
    const float* z          = (const float*)d_in[4];
    const float* occ_body   = (const float*)d_in[5];
    const float* occ_face   = (const float*)d_in[6];
    float* out = (float*)d_out;

    (void)in_sizes; (void)n_in; (void)out_size;

    // 1) per-row nearest-zero distance (ballot / bit-scan)
    row_dist_kernel<<<NB * IMH, IMW>>>(mask);
    // 2) Chebyshev DT column combine + pack fusion record
    col_pack_kernel<<<(NB * IMH * IMW) / 256, 256>>>(face_depth, edge_mask);
    // 3) fused sampling + fusion (4 x 8B gathers per query)
    fuse_kernel<<<(NB * NQ + 255) / 256, 256>>>(xy, z, occ_body, occ_face, out);
}

// round 6
// speedup vs baseline: 1.5595x; 1.3968x over previous
#include <cuda_runtime.h>
#include <math.h>

#define IMW 1024
#define IMH 1024
#define NB 4
#define NQ 262144      // queries per batch (2^18)
#define DCAP 46        // distances >= 46 all map to weight 1.0
#define NPIX ((size_t)NB * IMH * IMW)

// Scratch (device globals — no allocation allowed)
__device__ uchar4 g_h4[NPIX / 4];   // per-row nearest-zero distance, capped (4 px packed)
__device__ uint4  g_p4[NPIX / 2];   // packed {depth f32, edge|code<<8} x2 pixels per uint4

// ---------------------------------------------------------------------------
// Kernel 1: per-row 1D distance to nearest zero, capped at DCAP.
// One block = one row, 256 threads, 4 pixels/thread (float4 loads).
// Zero flags -> 1024-bit bitmap in smem (nibble shuffle-OR), then ONE pair of
// 64-bit windows per thread serves all 4 pixels (ffsll per pixel only).
// ---------------------------------------------------------------------------
__global__ void row_dist_kernel(const float4* __restrict__ mask4) {
    __shared__ unsigned int zw[32];
    const int row = blockIdx.x;                      // 0 .. NB*IMH-1
    const int t = threadIdx.x;                       // 0 .. 255
    const int lane = t & 31;

    const float4 v = mask4[(size_t)row * 256 + t];
    unsigned int nib = (v.x == 0.0f ? 1u : 0u)
                     | (v.y == 0.0f ? 2u : 0u)
                     | (v.z == 0.0f ? 4u : 0u)
                     | (v.w == 0.0f ? 8u : 0u);
    unsigned int val = nib << (4 * (lane & 7));
    // OR-reduce within each 8-lane group
    val |= __shfl_xor_sync(0xFFFFFFFFu, val, 1);
    val |= __shfl_xor_sync(0xFFFFFFFFu, val, 2);
    val |= __shfl_xor_sync(0xFFFFFFFFu, val, 4);
    if ((lane & 7) == 0) zw[(t >> 5) * 4 + (lane >> 3)] = val;
    __syncthreads();

    const int p = t * 4;            // first pixel of this thread

    // Right window: bit k = zeroflag(p + k), k in [0, 63]
    {
    }
    const int wp = p >> 5;
    const int off = p & 31;
    const unsigned int w0 = zw[wp];
    const unsigned int w1 = (wp + 1 < 32) ? zw[wp + 1] : 0u;
    const unsigned int w2 = (wp + 2 < 32) ? zw[wp + 2] : 0u;
    const unsigned long long rlo = (unsigned long long)w0 | ((unsigned long long)w1 << 32);
    unsigned long long R = off ? ((rlo >> off) | ((unsigned long long)w2 << (64 - off))) : rlo;

    // Left window anchored at q = p+3: bit k = zeroflag(q - k), k in [0, 63]
    const int q = p + 3;
    const int wq = q >> 5;
    const int offq = q & 31;
    const unsigned int rv0 = __brev(zw[wq]);
    const unsigned int rv1 = (wq >= 1) ? __brev(zw[wq - 1]) : 0u;
    const unsigned int rv2 = (wq >= 2) ? __brev(zw[wq - 2]) : 0u;
    const unsigned long long llo = (unsigned long long)rv0 | ((unsigned long long)rv1 << 32);
    unsigned long long L = (offq == 31) ? llo
                         : ((llo >> (31 - offq)) | ((unsigned long long)rv2 << (33 + offq)));

    uchar4 out;
    #pragma unroll
    for (int j = 0; j < 4; ++j) {
        const unsigned long long Rj = R >> j;
        const unsigned long long Lj = L >> (3 - j);
        const int rd = Rj ? (__ffsll((long long)Rj) - 1) : 64;
        const int ld = Lj ? (__ffsll((long long)Lj) - 1) : 64;
        int h = min(rd, ld);
        h = min(h, DCAP);
        ((unsigned char*)&out)[j] = (unsigned char)h;
    }
    g_h4[(size_t)row * 256 + t] = out;
}

// ---------------------------------------------------------------------------
// Kernel 2: Chebyshev DT column combine + pack per-pixel fusion record.
// 4 pixels/thread, vector loads/stores. d(x,y)=min_r max(r, min(h[y-r],h[y+r]))
// with early exit (at 50% mask density the loop almost never runs).
// ---------------------------------------------------------------------------
__global__ void col_pack_kernel(const float4* __restrict__ depth4,
                                const float4* __restrict__ edge4) {
    const int tid = blockIdx.x * blockDim.x + threadIdx.x;   // 0 .. NPIX/4-1
    const int x4 = tid & 255;
    const int y  = (tid >> 8) & (IMH - 1);
    const int b  = tid >> 18;
    const size_t rowbase = (size_t)b * IMH * 256;

    const uchar4 hv = g_h4[tid];
    int b0 = hv.x, b1 = hv.y, b2 = hv.z, b3 = hv.w;
    int bmax = max(max(b0, b1), max(b2, b3));

    #pragma unroll 1
    for (int r = 1; r < bmax; ++r) {
        const int yu = y - r;
        const int yd = y + r;
        int u0 = DCAP, u1 = DCAP, u2 = DCAP, u3 = DCAP;
        if (yu >= 0) {
            const uchar4 up = g_h4[rowbase + (size_t)yu * 256 + x4];
            u0 = up.x; u1 = up.y; u2 = up.z; u3 = up.w;
        }
        if (yd < IMH) {
            const uchar4 dn = g_h4[rowbase + (size_t)yd * 256 + x4];
            u0 = min(u0, (int)dn.x); u1 = min(u1, (int)dn.y);
            u2 = min(u2, (int)dn.z); u3 = min(u3, (int)dn.w);
        }
        b0 = min(b0, max(r, u0)); b1 = min(b1, max(r, u1));
        b2 = min(b2, max(r, u2)); b3 = min(b3, max(r, u3));
        bmax = max(max(b0, b1), max(b2, b3));
    }

    // weight code: 0 -> weight 0 (d==0); else 1 + min(15, (d-1)/3)
    const int c0 = b0 ? (1 + min(15, (b0 - 1) / 3)) : 0;
    const int c1 = b1 ? (1 + min(15, (b1 - 1) / 3)) : 0;
    const int c2 = b2 ? (1 + min(15, (b2 - 1) / 3)) : 0;
    const int c3 = b3 ? (1 + min(15, (b3 - 1) / 3)) : 0;

    const float4 e = edge4[tid];
    const float4 d = depth4[tid];

    uint4 pa, pb;
    pa.x = __float_as_uint(d.x);
    pa.y = (e.x != 0.0f ? 1u : 0u) | ((unsigned int)c0 << 8);
    pa.z = __float_as_uint(d.y);
    pa.w = (e.y != 0.0f ? 1u : 0u) | ((unsigned int)c1 << 8);
    pb.x = __float_as_uint(d.z);
    pb.y = (e.z != 0.0f ? 1u : 0u) | ((unsigned int)c2 << 8);
    pb.z = __float_as_uint(d.w);
    pb.w = (e.w != 0.0f ? 1u : 0u) | ((unsigned int)c3 << 8);
    g_p4[(size_t)tid * 2]     = pa;
    g_p4[(size_t)tid * 2 + 1] = pb;
}

// ---------------------------------------------------------------------------
// Kernel 3: fused bilinear sampling + psdf weighting + occupancy fusion.
// One thread per query; 4 x 8B gathers (L2-resident, 32MB packed image).
// ---------------------------------------------------------------------------
__global__ void fuse_kernel(const float* __restrict__ xy,
                            const float* __restrict__ z,
                            const float* __restrict__ occ_body,
                            const float* __restrict__ occ_face,
                            float* __restrict__ out) {
    const int i = blockIdx.x * blockDim.x + threadIdx.x;
    if (i >= NB * NQ) return;
    const int b = i >> 18;            // i / NQ
    const int n = i & (NQ - 1);       // i % NQ
    const uint2* __restrict__ gp = (const uint2*)g_p4;

    const float px = xy[(size_t)b * 2 * NQ + n];
    const float py = xy[(size_t)b * 2 * NQ + NQ + n];

    const float gx = (px + 1.0f) * 0.5f * (float)(IMW - 1);
    const float gy = (py + 1.0f) * 0.5f * (float)(IMH - 1);
    const float x0f = floorf(gx);
    const float y0f = floorf(gy);
    const float wx = gx - x0f;
    const float wy = gy - y0f;

    const int x0 = (int)fminf(fmaxf(x0f,        0.0f), (float)(IMW - 1));
    const int x1 = (int)fminf(fmaxf(x0f + 1.0f, 0.0f), (float)(IMW - 1));
    const int y0 = (int)fminf(fmaxf(y0f,        0.0f), (float)(IMH - 1));
    const int y1 = (int)fminf(fmaxf(y0f + 1.0f, 0.0f), (float)(IMH - 1));

    const size_t base = (size_t)b * IMH * IMW;
    const uint2 u00 = __ldg(&gp[base + (size_t)y0 * IMW + x0]);
    const uint2 u10 = __ldg(&gp[base + (size_t)y0 * IMW + x1]);
    const uint2 u01 = __ldg(&gp[base + (size_t)y1 * IMW + x0]);
    const uint2 u11 = __ldg(&gp[base + (size_t)y1 * IMW + x1]);

    const float w00 = (1.0f - wx) * (1.0f - wy);
    const float w10 = wx * (1.0f - wy);
    const float w01 = (1.0f - wx) * wy;
    const float w11 = wx * wy;

    // edge bilinear (values are exact 0.0/1.0 -> identical to reference fp32)
    const float edge = (float)(u00.y & 0xFFu) * w00 + (float)(u10.y & 0xFFu) * w10
                     + (float)(u01.y & 0xFFu) * w01 + (float)(u11.y & 0xFFu) * w11;

    // depth bilinear
    const float dq = __uint_as_float(u00.x) * w00 + __uint_as_float(u10.x) * w10
                   + __uint_as_float(u01.x) * w01 + __uint_as_float(u11.x) * w11;

    // erosion-weight bilinear (reconstruct fp32 weight from code)
    const int c00 = (int)(u00.y >> 8), c10 = (int)(u10.y >> 8);
    const int c01 = (int)(u01.y >> 8), c11 = (int)(u11.y >> 8);
    const float v00 = c00 ? (0.1f + 0.06f * (float)(c00 - 1)) : 0.0f;
    const float v10 = c10 ? (0.1f + 0.06f * (float)(c10 - 1)) : 0.0f;
    const float v01 = c01 ? (0.1f + 0.06f * (float)(c01 - 1)) : 0.0f;
    const float v11 = c11 ? (0.1f + 0.06f * (float)(c11 - 1)) : 0.0f;
    const float lab = v00 * w00 + v10 * w10 + v01 * w01 + v11 * w11;

    const float eb = (edge > 0.01f) ? 1.0f : 0.0f;
    const float psdf = z[i] - dq * eb;
    const float w = expf(-psdf * psdf * 1000.0f) * lab * eb;

    const float ob = occ_body[i];
    out[i] = w * occ_face[i] + (1.0f - w) * ob;
}

// ---------------------------------------------------------------------------
extern "C" void kernel_launch(void* const* d_in, const int* in_sizes, int n_in,
                              void* d_out, int out_size) {
    const float* mask       = (const float*)d_in[0];
    const float* face_depth = (const float*)d_in[1];
    const float* edge_mask  = (const float*)d_in[2];
    const float* xy         = (const float*)d_in[3];
    const float* z          = (const float*)d_in[4];
    const float* occ_body   = (const float*)d_in[5];
    const float* occ_face   = (const float*)d_in[6];
    float* out = (float*)d_out;

    (void)in_sizes; (void)n_in; (void)out_size;

    // 1) per-row nearest-zero distance (bitmap + shared windows, 4 px/thread)
    row_dist_kernel<<<NB * IMH, 256>>>((const float4*)mask);
    // 2) Chebyshev DT column combine + pack fusion record (4 px/thread)
    col_pack_kernel<<<(NPIX / 4) / 256, 256>>>((const float4*)face_depth,
                                               (const float4*)edge_mask);
    // 3) fused sampling + fusion (4 x 8B gathers per query)
    fuse_kernel<<<(NB * NQ + 255) / 256, 256>>>(xy, z, occ_body, occ_face, out);
}

// round 7
// speedup vs baseline: 1.9780x; 1.2684x over previous
#include <cuda_runtime.h>
#include <math.h>

#define IMW 1024
#define IMH 1024
#define NB 4
#define NQ 262144      // queries per batch (2^18)
#define DCAP 46        // distances >= 46 all map to weight 1.0
#define NPIX ((size_t)NB * IMH * IMW)

// Scratch (device globals — no allocation allowed)
__device__ unsigned long long g_h8[NPIX / 8];  // row nearest-zero distances, 8 px/word
__device__ uint4 g_p4[NPIX / 4];               // packed 4B records: depth(f32, low 6 mantissa bits = payload)

// ---------------------------------------------------------------------------
// Kernel 1: per-row 1D distance to nearest zero, capped at DCAP.
// 2 rows per 256-thread block, 8 px/thread. Zero flags -> 1024-bit bitmap in
// smem (byte shift + shfl-OR). One 64-bit R window + one L window (anchored at
// p+7) serve all 8 pixels; per pixel: h = ffsll((R>>j) | (L>>(7-j))) - 1.
// ---------------------------------------------------------------------------
__global__ void row_dist_kernel(const float4* __restrict__ mask4) {
    __shared__ unsigned int zw[2][32];
    const int t = threadIdx.x;                       // 0 .. 255
    const int half = t >> 7;                         // row within block
    const int tr = t & 127;                          // thread within row
    const int lane = t & 31;
    const int row = blockIdx.x * 2 + half;           // 0 .. NB*IMH-1

    const float4 va = mask4[(size_t)row * 256 + tr * 2];
    const float4 vb = mask4[(size_t)row * 256 + tr * 2 + 1];
    unsigned int byte = (va.x == 0.0f ? 1u : 0u)
                      | (va.y == 0.0f ? 2u : 0u)
                      | (va.z == 0.0f ? 4u : 0u)
                      | (va.w == 0.0f ? 8u : 0u)
                      | (vb.x == 0.0f ? 16u : 0u)
                      | (vb.y == 0.0f ? 32u : 0u)
                      | (vb.z == 0.0f ? 64u : 0u)
                      | (vb.w == 0.0f ? 128u : 0u);
    unsigned int val = byte << (8 * (lane & 3));
    val |= __shfl_xor_sync(0xFFFFFFFFu, val, 1);
    val |= __shfl_xor_sync(0xFFFFFFFFu, val, 2);
    if ((lane & 3) == 0) zw[half][tr >> 2] = val;
    __syncthreads();

    const int p = tr * 8;                            // first pixel of this thread

    // Right window: bit k = zeroflag(p + k), k in [0, 63]
    const int wp = p >> 5;
    const int off = p & 31;                          // 0, 8, 16, 24
    const unsigned int w0 = zw[half][wp];
    const unsigned int w1 = (wp + 1 < 32) ? zw[half][wp + 1] : 0u;
    const unsigned int w2 = (wp + 2 < 32) ? zw[half][wp + 2] : 0u;
    const unsigned long long rlo = (unsigned long long)w0 | ((unsigned long long)w1 << 32);
    unsigned long long R = rlo >> off;
    if (off) R |= (unsigned long long)w2 << (64 - off);

    // Left window anchored at q = p+7: bit k = zeroflag(q - k), k in [0, 63]
    const int q = p + 7;
    const int wq = q >> 5;
    const int sh = 31 - (q & 31);                    // 24, 16, 8, 0
    const unsigned int rv0 = __brev(zw[half][wq]);
    const unsigned int rv1 = (wq >= 1) ? __brev(zw[half][wq - 1]) : 0u;
    const unsigned int rv2 = (wq >= 2) ? __brev(zw[half][wq - 2]) : 0u;
    const unsigned long long llo = (unsigned long long)rv0 | ((unsigned long long)rv1 << 32);
    unsigned long long L = llo >> sh;
    if (sh) L |= (unsigned long long)rv2 << (64 - sh);

    unsigned long long packed = 0;
    #pragma unroll
    for (int j = 0; j < 8; ++j) {
        const unsigned long long C = (R >> j) | (L >> (7 - j));
        int h = C ? (__ffsll((long long)C) - 1) : DCAP;
        h = min(h, DCAP);
        packed |= (unsigned long long)h << (8 * j);
    }
    g_h8[(size_t)row * 128 + tr] = packed;
}

// ---------------------------------------------------------------------------
// Kernel 2: Chebyshev DT column combine + pack per-pixel 4B fusion record.
// 4 px/thread. d(x,y) = min_r max(r, min(h[y-r], h[y+r])), early exit.
// Record: depth f32 with low 6 mantissa bits = (code<<1)|edge, code in 0..16,
// depth rounded-to-nearest at bit 6 (<= 32 ulp = 1.9e-6 relative error).
// ---------------------------------------------------------------------------
__global__ void col_pack_kernel(const float4* __restrict__ depth4,
                                const float4* __restrict__ edge4) {
    const int tid = blockIdx.x * blockDim.x + threadIdx.x;   // 0 .. NPIX/4-1
    const int x4 = tid & 255;
    const int y  = (tid >> 8) & (IMH - 1);
    const int b  = tid >> 18;
    const uchar4* __restrict__ hv4 = (const uchar4*)g_h8;
    const size_t rowbase = (size_t)b * IMH * 256;

    const uchar4 hv = hv4[tid];
    int b0 = hv.x, b1 = hv.y, b2 = hv.z, b3 = hv.w;
    int bmax = max(max(b0, b1), max(b2, b3));

    #pragma unroll 1
    for (int r = 1; r < bmax; ++r) {
        const int yu = y - r;
        const int yd = y + r;
        int u0 = DCAP, u1 = DCAP, u2 = DCAP, u3 = DCAP;
        if (yu >= 0) {
            const uchar4 up = hv4[rowbase + (size_t)yu * 256 + x4];
            u0 = up.x; u1 = up.y; u2 = up.z; u3 = up.w;
        }
        if (yd < IMH) {
            const uchar4 dn = hv4[rowbase + (size_t)yd * 256 + x4];
            u0 = min(u0, (int)dn.x); u1 = min(u1, (int)dn.y);
            u2 = min(u2, (int)dn.z); u3 = min(u3, (int)dn.w);
        }
        b0 = min(b0, max(r, u0)); b1 = min(b1, max(r, u1));
        b2 = min(b2, max(r, u2)); b3 = min(b3, max(r, u3));
        bmax = max(max(b0, b1), max(b2, b3));
    }

    // weight code: 0 -> weight 0 (d==0); else 1 + min(15, (d-1)/3)   (0..16)
    const unsigned int c0 = b0 ? (1 + min(15, (b0 - 1) / 3)) : 0;
    const unsigned int c1 = b1 ? (1 + min(15, (b1 - 1) / 3)) : 0;
    const unsigned int c2 = b2 ? (1 + min(15, (b2 - 1) / 3)) : 0;
    const unsigned int c3 = b3 ? (1 + min(15, (b3 - 1) / 3)) : 0;

    const float4 e = edge4[tid];
    const float4 d = depth4[tid];

    uint4 p;
    p.x = ((__float_as_uint(d.x) + 32u) & ~63u) | (c0 << 1) | (e.x != 0.0f ? 1u : 0u);
    p.y = ((__float_as_uint(d.y) + 32u) & ~63u) | (c1 << 1) | (e.y != 0.0f ? 1u : 0u);
    p.z = ((__float_as_uint(d.z) + 32u) & ~63u) | (c2 << 1) | (e.z != 0.0f ? 1u : 0u);
    p.w = ((__float_as_uint(d.w) + 32u) & ~63u) | (c3 << 1) | (e.w != 0.0f ? 1u : 0u);
    g_p4[tid] = p;
}

// ---------------------------------------------------------------------------
// Kernel 3: fused bilinear sampling + psdf weighting + occupancy fusion.
// One thread per query; 4 x 4B gathers into a 16MB L2-resident packed image.
// ---------------------------------------------------------------------------
__global__ void fuse_kernel(const float* __restrict__ xy,
                            const float* __restrict__ z,
                            const float* __restrict__ occ_body,
                            const float* __restrict__ occ_face,
                            float* __restrict__ out) {
    const int i = blockIdx.x * blockDim.x + threadIdx.x;
    if (i >= NB * NQ) return;
    const int b = i >> 18;            // i / NQ
    const int n = i & (NQ - 1);       // i % NQ
    const unsigned int* __restrict__ gp = (const unsigned int*)g_p4;

    const float px = xy[(size_t)b * 2 * NQ + n];
    const float py = xy[(size_t)b * 2 * NQ + NQ + n];

    const float gx = (px + 1.0f) * 0.5f * (float)(IMW - 1);
    const float gy = (py + 1.0f) * 0.5f * (float)(IMH - 1);
    const float x0f = floorf(gx);
    const float y0f = floorf(gy);
    const float wx = gx - x0f;
    const float wy = gy - y0f;

    const int x0 = (int)fminf(fmaxf(x0f,        0.0f), (float)(IMW - 1));
    const int x1 = (int)fminf(fmaxf(x0f + 1.0f, 0.0f), (float)(IMW - 1));
    const int y0 = (int)fminf(fmaxf(y0f,        0.0f), (float)(IMH - 1));
    const int y1 = (int)fminf(fmaxf(y0f + 1.0f, 0.0f), (float)(IMH - 1));

    const size_t base = (size_t)b * IMH * IMW;
    const unsigned int u00 = __ldg(&gp[base + (size_t)y0 * IMW + x0]);
    const unsigned int u10 = __ldg(&gp[base + (size_t)y0 * IMW + x1]);
    const unsigned int u01 = __ldg(&gp[base + (size_t)y1 * IMW + x0]);
    const unsigned int u11 = __ldg(&gp[base + (size_t)y1 * IMW + x1]);

    const float w00 = (1.0f - wx) * (1.0f - wy);
    const float w10 = wx * (1.0f - wy);
    const float w01 = (1.0f - wx) * wy;
    const float w11 = wx * wy;

    // edge bilinear (values are exact 0.0/1.0 -> identical to reference fp32)
    const float edge = (float)(u00 & 1u) * w00 + (float)(u10 & 1u) * w10
                     + (float)(u01 & 1u) * w01 + (float)(u11 & 1u) * w11;

    // depth bilinear (payload bits masked out; <=32 ulp quantization)
    const float dq = __uint_as_float(u00 & ~63u) * w00 + __uint_as_float(u10 & ~63u) * w10
                   + __uint_as_float(u01 & ~63u) * w01 + __uint_as_float(u11 & ~63u) * w11;

    // erosion-weight bilinear (reconstruct fp32 weight from 5-bit code)
    const int c00 = (int)((u00 >> 1) & 31u), c10 = (int)((u10 >> 1) & 31u);
    const int c01 = (int)((u01 >> 1) & 31u), c11 = (int)((u11 >> 1) & 31u);
    const float v00 = c00 ? (0.1f + 0.06f * (float)(c00 - 1)) : 0.0f;
    const float v10 = c10 ? (0.1f + 0.06f * (float)(c10 - 1)) : 0.0f;
    const float v01 = c01 ? (0.1f + 0.06f * (float)(c01 - 1)) : 0.0f;
    const float v11 = c11 ? (0.1f + 0.06f * (float)(c11 - 1)) : 0.0f;
    const float lab = v00 * w00 + v10 * w10 + v01 * w01 + v11 * w11;

    const float eb = (edge > 0.01f) ? 1.0f : 0.0f;
    const float psdf = z[i] - dq * eb;
    const float w = expf(-psdf * psdf * 1000.0f) * lab * eb;

    const float ob = occ_body[i];
    out[i] = w * occ_face[i] + (1.0f - w) * ob;
}

// ---------------------------------------------------------------------------
extern "C" void kernel_launch(void* const* d_in, const int* in_sizes, int n_in,
                              void* d_out, int out_size) {
    const float* mask       = (const float*)d_in[0];
    const float* face_depth = (const float*)d_in[1];
    const float* edge_mask  = (const float*)d_in[2];
    const float* xy         = (const float*)d_in[3];
    const float* z          = (const float*)d_in[4];
    const float* occ_body   = (const float*)d_in[5];
    const float* occ_face   = (const float*)d_in[6];
    float* out = (float*)d_out;

    (void)in_sizes; (void)n_in; (void)out_size;

    // 1) per-row nearest-zero distance (bitmap + shared windows, 8 px/thread)
    row_dist_kernel<<<NB * IMH / 2, 256>>>((const float4*)mask);
    // 2) Chebyshev DT column combine + 4B record pack (4 px/thread)
    col_pack_kernel<<<(NPIX / 4) / 256, 256>>>((const float4*)face_depth,
                                               (const float4*)edge_mask);
    // 3) fused sampling + fusion (4 x 4B gathers per query)
    fuse_kernel<<<(NB * NQ + 255) / 256, 256>>>(xy, z, occ_body, occ_face, out);
}

// round 10
// speedup vs baseline: 2.1219x; 1.0727x over previous
#include <cuda_runtime.h>
#include <math.h>

#define IMW 1024
#define IMH 1024
#define NB 4
#define NQ 262144      // queries per batch (2^18)
#define DCAP 46        // distances >= 46 all map to weight 1.0
#define NPIX ((size_t)NB * IMH * IMW)

// Scratch (device globals — no allocation allowed). uint4 type guarantees 16B alignment.
__device__ uint4 g_h4[NPIX / 16];   // row nearest-zero distances, 1 byte/px
__device__ uint4 g_p4[NPIX / 4];    // packed 4B records: depth f32, low 6 mantissa bits = (code<<1)|edge

// movemask of "pixel == 0.0f" for 4 packed float words (values are exactly 0.0f or 1.0f)
__device__ __forceinline__ unsigned int movemask_zero4(unsigned int x, unsigned int y,
                                                       unsigned int z, unsigned int w) {
    const unsigned int t01 = __byte_perm(x, y, 0x0073);    // [x.b3, y.b3, ., .]
    const unsigned int t23 = __byte_perm(z, w, 0x0073);    // [z.b3, w.b3, ., .]
    const unsigned int tops = __byte_perm(t01, t23, 0x5410); // [x.b3,y.b3,z.b3,w.b3]
    // 1.0f top byte = 0x3F (bit5=1); 0.0f -> 0x00 (bit5=0)
    const unsigned int u = (~tops) & 0x20202020u;          // 0x20 per zero pixel
    return ((u >> 5) * 0x01020408u) >> 24;                 // 4-bit movemask (bit k <-> px k)
}

// ---------------------------------------------------------------------------
// Kernel 1: per-row 1D distance to nearest zero, capped at DCAP.
// One warp per row, 32 px/thread. Flags = one 32-bit word per thread; neighbor
// words via shfl (row == warp, so no smem / no __syncthreads). Windows are
// bit-reversed so h = clz(R|L); constant funnel shifts via full unroll.
// Distances >= 32 (prob ~2^-60 per px) handled by an exact rare path.
// ---------------------------------------------------------------------------
__global__ void row_dist_kernel(const uint4* __restrict__ mask4) {
    const int lane = threadIdx.x & 31;
    const int row = blockIdx.x * 8 + (threadIdx.x >> 5);     // 8 rows per 256-thr block
    const uint4* mrow = mask4 + (size_t)row * 256 + lane * 8;

    // Build 32-bit zero-flag word (bit i <-> pixel lane*32 + i)
    unsigned int w = 0;
    #pragma unroll
    for (int k = 0; k < 8; ++k) {
        const uint4 v = mrow[k];
        w |= movemask_zero4(v.x, v.y, v.z, v.w) << (4 * k);
    }

    // Neighbor flag words (0 beyond row edge: no pixels -> no zeros there)
    unsigned int wR1 = __shfl_down_sync(~0u, w, 1); if (lane >= 31) wR1 = 0;
    unsigned int wR2 = __shfl_down_sync(~0u, w, 2); if (lane >= 30) wR2 = 0;
    unsigned int wL1 = __shfl_up_sync(~0u, w, 1);   if (lane <  1) wL1 = 0;
    unsigned int wL2 = __shfl_up_sync(~0u, w, 2);   if (lane <  2) wL2 = 0;

    const unsigned int bw  = __brev(w);
    const unsigned int bw1 = __brev(wR1);

    unsigned int g[8];
    unsigned int slowmask = 0;
    #pragma unroll
    for (int j = 0; j < 32; ++j) {
        // Rrev: bit(31-k) = flag[p+j+k];  Lrev: bit(31-k) = flag[p+j-k]
        const unsigned int Rrev = (j == 0)  ? bw : __funnelshift_r(bw1, bw, 32 - j);
        const unsigned int Lrev = (j == 31) ? w  : __funnelshift_r(wL1, w, j + 1);
        const unsigned int C = Rrev | Lrev;
        const unsigned int h = __clz(C);                 // exact if < 32; 32 -> rare path
        if ((j & 3) == 0) g[j >> 2] = h;
        else              g[j >> 2] |= h << (8 * (j & 3));
        slowmask |= (C == 0 ? 1u : 0u) << j;
    }

    if (slowmask) {   // ~never taken (needs a 63+ run of ones); exact fallback
        #pragma unroll 1
        for (int j = 0; j < 32; ++j) {
            if ((slowmask >> j) & 1u) {
                int h = DCAP;
                #pragma unroll 1
                for (int r = 32; r < DCAP; ++r) {
                    const int ir = j + r;              // in [32, 76]
                    const int il = j - r;              // in [-46, -1]
                    const unsigned int fr = (ir < 64) ? ((wR1 >> (ir - 32)) & 1u)
                                                      : ((wR2 >> (ir - 64)) & 1u);
                    const unsigned int fl = (il >= -32) ? ((wL1 >> (il + 32)) & 1u)
                                                        : ((wL2 >> (il + 64)) & 1u);
                    if (fr | fl) { h = r; break; }
                }
                const int sh = 8 * (j & 3);
                g[j >> 2] = (g[j >> 2] & ~(0xFFu << sh)) | ((unsigned int)h << sh);
            }
        }
    }

    uint4* out = g_h4 + (size_t)row * 64 + lane * 2;
    out[0] = make_uint4(g[0], g[1], g[2], g[3]);
    out[1] = make_uint4(g[4], g[5], g[6], g[7]);
}

// ---------------------------------------------------------------------------
// Kernel 2: Chebyshev DT column combine (SIMD bytes) + pack 4B fusion records.
// 8 px/thread. d(x,y) = min_r max(r, min(h[y-r], h[y+r])), early exit.
// ---------------------------------------------------------------------------
__device__ __forceinline__ unsigned int hmax8(unsigned int a, unsigned int b) {
    unsigned int m = __vmaxu4(a, b);
    m = __vmaxu4(m, m >> 16);
    m = __vmaxu4(m, m >> 8);
    return m & 0xFFu;
}

__device__ __forceinline__ unsigned int make_rec(unsigned int dbits, unsigned int ebits,
                                                 unsigned int b8) {
    // code = floor((d+2)/3) in 0..16 (exact via *171>>9 for d<=46); edge bit from f32 0/1
    const unsigned int c = ((b8 + 2u) * 171u) >> 9;
    return ((dbits + 32u) & ~63u) | (c << 1) | ((ebits >> 29) & 1u);
}

__global__ void col_pack_kernel(const uint4* __restrict__ depth4,
                                const uint4* __restrict__ edge4) {
    const int tid = blockIdx.x * blockDim.x + threadIdx.x;   // 0 .. NPIX/8-1
    const int y = (tid >> 7) & (IMH - 1);
    const unsigned long long* gh = (const unsigned long long*)g_h4;
    const size_t cbase = ((size_t)(tid >> 17) << 17) + (tid & 127); // b*131072 + x8

    const unsigned long long hv = gh[tid];
    unsigned int blo = (unsigned int)hv, bhi = (unsigned int)(hv >> 32);
    unsigned int bmax = hmax8(blo, bhi);

    #pragma unroll 1
    for (unsigned int r = 1; r < bmax; ++r) {
        const int yu = y - (int)r;
        const int yd = y + (int)r;
        unsigned int ulo = 0x2E2E2E2Eu, uhi = 0x2E2E2E2Eu;   // DCAP bytes
        if (yu >= 0) {
            const unsigned long long hu = gh[cbase + (size_t)yu * 128];
            ulo = (unsigned int)hu; uhi = (unsigned int)(hu >> 32);
        }
        if (yd < IMH) {
            const unsigned long long hd = gh[cbase + (size_t)yd * 128];
            ulo = __vminu4(ulo, (unsigned int)hd);
            uhi = __vminu4(uhi, (unsigned int)(hd >> 32));
        }
        const unsigned int rq = r * 0x01010101u;
        blo = __vminu4(blo, __vmaxu4(ulo, rq));
        bhi = __vminu4(bhi, __vmaxu4(uhi, rq));
        bmax = hmax8(blo, bhi);
    }

    const uint4 d0 = depth4[tid * 2], d1 = depth4[tid * 2 + 1];
    const uint4 e0 = edge4[tid * 2],  e1 = edge4[tid * 2 + 1];

    uint4 pA, pB;
    pA.x = make_rec(d0.x, e0.x,  blo        & 0xFFu);
    pA.y = make_rec(d0.y, e0.y, (blo >>  8) & 0xFFu);
    pA.z = make_rec(d0.z, e0.z, (blo >> 16) & 0xFFu);
    pA.w = make_rec(d0.w, e0.w,  blo >> 24);
    pB.x = make_rec(d1.x, e1.x,  bhi        & 0xFFu);
    pB.y = make_rec(d1.y, e1.y, (bhi >>  8) & 0xFFu);
    pB.z = make_rec(d1.z, e1.z, (bhi >> 16) & 0xFFu);
    pB.w = make_rec(d1.w, e1.w,  bhi >> 24);
    g_p4[tid * 2]     = pA;
    g_p4[tid * 2 + 1] = pB;
}

// ---------------------------------------------------------------------------
// Kernel 3: fused bilinear sampling + psdf weighting + occupancy fusion.
// 2 queries/thread (float2 I/O, 8 outstanding 4B gathers into 16MB L2 image).
// ---------------------------------------------------------------------------
__device__ __forceinline__ float fuse_one(int b, float px, float py, float zz,
                                          float ob, float of) {
    const unsigned int* __restrict__ gp = (const unsigned int*)g_p4;

    const float gx = (px + 1.0f) * 0.5f * (float)(IMW - 1);
    const float gy = (py + 1.0f) * 0.5f * (float)(IMH - 1);
    const float x0f = floorf(gx);
    const float y0f = floorf(gy);
    const float wx = gx - x0f;
    const float wy = gy - y0f;

    const int x0 = (int)fminf(fmaxf(x0f,        0.0f), (float)(IMW - 1));
    const int x1 = (int)fminf(fmaxf(x0f + 1.0f, 0.0f), (float)(IMW - 1));
    const int y0 = (int)fminf(fmaxf(y0f,        0.0f), (float)(IMH - 1));
    const int y1 = (int)fminf(fmaxf(y0f + 1.0f, 0.0f), (float)(IMH - 1));

    const size_t base = (size_t)b * IMH * IMW;
    const unsigned int u00 = __ldg(&gp[base + (size_t)y0 * IMW + x0]);
    const unsigned int u10 = __ldg(&gp[base + (size_t)y0 * IMW + x1]);
    const unsigned int u01 = __ldg(&gp[base + (size_t)y1 * IMW + x0]);
    const unsigned int u11 = __ldg(&gp[base + (size_t)y1 * IMW + x1]);

    const float w00 = (1.0f - wx) * (1.0f - wy);
    const float w10 = wx * (1.0f - wy);
    const float w01 = (1.0f - wx) * wy;
    const float w11 = wx * wy;

    const float edge = (float)(u00 & 1u) * w00 + (float)(u10 & 1u) * w10
                     + (float)(u01 & 1u) * w01 + (float)(u11 & 1u) * w11;

    const float dq = __uint_as_float(u00 & ~63u) * w00 + __uint_as_float(u10 & ~63u) * w10
                   + __uint_as_float(u01 & ~63u) * w01 + __uint_as_float(u11 & ~63u) * w11;

    const int c00 = (int)((u00 >> 1) & 31u), c10 = (int)((u10 >> 1) & 31u);
    const int c01 = (int)((u01 >> 1) & 31u), c11 = (int)((u11 >> 1) & 31u);
    const float v00 = c00 ? (0.1f + 0.06f * (float)(c00 - 1)) : 0.0f;
    const float v10 = c10 ? (0.1f + 0.06f * (float)(c10 - 1)) : 0.0f;
    const float v01 = c01 ? (0.1f + 0.06f * (float)(c01 - 1)) : 0.0f;
    const float v11 = c11 ? (0.1f + 0.06f * (float)(c11 - 1)) : 0.0f;
    const float lab = v00 * w00 + v10 * w10 + v01 * w01 + v11 * w11;

    const float eb = (edge > 0.01f) ? 1.0f : 0.0f;
    const float psdf = zz - dq * eb;
    const float w = expf(-psdf * psdf * 1000.0f) * lab * eb;
    return w * of + (1.0f - w) * ob;
}

__global__ void fuse_kernel(const float* __restrict__ xy,
                            const float* __restrict__ z,
                            const float* __restrict__ occ_body,
                            const float* __restrict__ occ_face,
                            float* __restrict__ out) {
    const int t = blockIdx.x * blockDim.x + threadIdx.x;     // 0 .. NB*NQ/2-1
    const int i0 = t * 2;
    const int b = i0 >> 18;
    const int n0 = i0 & (NQ - 1);

    const float2 xs = *(const float2*)(xy + (size_t)b * 2 * NQ + n0);
    const float2 ys = *(const float2*)(xy + (size_t)b * 2 * NQ + NQ + n0);
    const float2 zs  = *(const float2*)(z + i0);
    const float2 obs = *(const float2*)(occ_body + i0);
    const float2 ofs = *(const float2*)(occ_face + i0);

    const float r0 = fuse_one(b, xs.x, ys.x, zs.x, obs.x, ofs.x);
    const float r1 = fuse_one(b, xs.y, ys.y, zs.y, obs.y, ofs.y);
    *(float2*)(out + i0) = make_float2(r0, r1);
}

// ---------------------------------------------------------------------------
extern "C" void kernel_launch(void* const* d_in, const int* in_sizes, int n_in,
                              void* d_out, int out_size) {
    const float* mask       = (const float*)d_in[0];
    const float* face_depth = (const float*)d_in[1];
    const float* edge_mask  = (const float*)d_in[2];
    const float* xy         = (const float*)d_in[3];
    const float* z          = (const float*)d_in[4];
    const float* occ_body   = (const float*)d_in[5];
    const float* occ_face   = (const float*)d_in[6];
    float* out = (float*)d_out;

    (void)in_sizes; (void)n_in; (void)out_size;

    // 1) per-row nearest-zero distance (warp-per-row, 32 px/thread, no smem)
    row_dist_kernel<<<NB * IMH / 8, 256>>>((const uint4*)mask);
    // 2) Chebyshev DT column combine + 4B record pack (8 px/thread, SIMD bytes)
    col_pack_kernel<<<(int)(NPIX / 8 / 256), 256>>>((const uint4*)face_depth,
                                                    (const uint4*)edge_mask);
    // 3) fused sampling + fusion (2 queries/thread, 8 gathers in flight)
    fuse_kernel<<<(NB * NQ / 2) / 256, 256>>>(xy, z, occ_body, occ_face, out);
}

// round 12
// speedup vs baseline: 2.2245x; 1.0483x over previous
#include <cuda_runtime.h>
#include <math.h>

#define IMW 1024
#define IMH 1024
#define NB 4
#define NQ 262144      // queries per batch (2^18)
#define DCAP 46        // distances >= 46 all map to weight 1.0
#define NPIX ((size_t)NB * IMH * IMW)

// Scratch (device globals — no allocation allowed). uint4 type guarantees 16B alignment.
__device__ uint4 g_h4[NPIX / 16];   // row nearest-zero distances, 1 byte/px
__device__ uint4 g_p4[NPIX / 4];    // packed 4B records: depth f32, low 6 mantissa bits = (code<<1)|edge

// movemask of "pixel == 0.0f" for 4 packed float words (values are exactly 0.0f or 1.0f)
__device__ __forceinline__ unsigned int movemask_zero4(unsigned int x, unsigned int y,
                                                       unsigned int z, unsigned int w) {
    const unsigned int t01 = __byte_perm(x, y, 0x0073);    // [x.b3, y.b3, ., .]
    const unsigned int t23 = __byte_perm(z, w, 0x0073);    // [z.b3, w.b3, ., .]
    const unsigned int tops = __byte_perm(t01, t23, 0x5410); // [x.b3,y.b3,z.b3,w.b3]
    // 1.0f top byte = 0x3F (bit5=1); 0.0f -> 0x00 (bit5=0)
    const unsigned int u = (~tops) & 0x20202020u;          // 0x20 per zero pixel
    return ((u >> 5) * 0x01020408u) >> 24;                 // 4-bit movemask (bit k <-> px k)
}

// ---------------------------------------------------------------------------
// Kernel 1: per-row 1D distance to nearest zero, capped at DCAP.
// One warp per row, 32 px/thread. COALESCED loads (thread reads uint4 k*32+lane)
// + 8-shfl warp transpose to give each thread its contiguous 32-pixel flag word.
// Windows are bit-reversed so h = clz(R|L); constant funnel shifts via unroll.
// Distances >= 32 (prob ~2^-60 per px) handled by an exact rare path.
// ---------------------------------------------------------------------------
__global__ void row_dist_kernel(const uint4* __restrict__ mask4) {
    const int lane = threadIdx.x & 31;
    const int row = blockIdx.x * 8 + (threadIdx.x >> 5);     // 8 rows per 256-thr block
    const uint4* mrow = mask4 + (size_t)row * 256;

    // Coalesced: thread reads uint4 index k*32+lane; nibble for that uint4 goes
    // to bits [4k, 4k+4) of nw.
    unsigned int nw = 0;
    #pragma unroll
    for (int k = 0; k < 8; ++k) {
        const uint4 v = mrow[k * 32 + lane];
        nw |= movemask_zero4(v.x, v.y, v.z, v.w) << (4 * k);
    }

    // Transpose: thread t needs uint4 indices t*8+m (m=0..7) -> slot k = t>>2
    // (constant per thread), source lane = (t&3)*8 + m.
    const int srcbase = (lane & 3) * 8;
    const int slotsh = (lane >> 2) * 4;
    unsigned int w = 0;
    #pragma unroll
    for (int m = 0; m < 8; ++m) {
        const unsigned int xm = __shfl_sync(~0u, nw, srcbase + m);
        w |= ((xm >> slotsh) & 0xFu) << (4 * m);
    }

    // Neighbor flag words (0 beyond row edge: no pixels -> no zeros there)
    unsigned int wR1 = __shfl_down_sync(~0u, w, 1); if (lane >= 31) wR1 = 0;
    unsigned int wR2 = __shfl_down_sync(~0u, w, 2); if (lane >= 30) wR2 = 0;
    unsigned int wL1 = __shfl_up_sync(~0u, w, 1);   if (lane <  1) wL1 = 0;
    unsigned int wL2 = __shfl_up_sync(~0u, w, 2);   if (lane <  2) wL2 = 0;

    const unsigned int bw  = __brev(w);
    const unsigned int bw1 = __brev(wR1);

    unsigned int g[8];
    unsigned int slowmask = 0;
    #pragma unroll
    for (int j = 0; j < 32; ++j) {
        // Rrev: bit(31-k) = flag[p+j+k];  Lrev: bit(31-k) = flag[p+j-k]
        const unsigned int Rrev = (j == 0)  ? bw : __funnelshift_r(bw1, bw, 32 - j);
        const unsigned int Lrev = (j == 31) ? w  : __funnelshift_r(wL1, w, j + 1);
        const unsigned int C = Rrev | Lrev;
        const unsigned int h = __clz(C);                 // exact if < 32; 32 -> rare path
        if ((j & 3) == 0) g[j >> 2] = h;
        else              g[j >> 2] |= h << (8 * (j & 3));
        slowmask |= (C == 0 ? 1u : 0u) << j;
    }

    if (slowmask) {   // ~never taken (needs a 63+ run of ones); exact fallback
        #pragma unroll 1
        for (int j = 0; j < 32; ++j) {
            if ((slowmask >> j) & 1u) {
                int h = DCAP;
                #pragma unroll 1
                for (int r = 32; r < DCAP; ++r) {
                    const int ir = j + r;              // in [32, 76]
                    const int il = j - r;              // in [-46, -1]
                    const unsigned int fr = (ir < 64) ? ((wR1 >> (ir - 32)) & 1u)
                                                      : ((wR2 >> (ir - 64)) & 1u);
                    const unsigned int fl = (il >= -32) ? ((wL1 >> (il + 32)) & 1u)
                                                        : ((wL2 >> (il + 64)) & 1u);
                    if (fr | fl) { h = r; break; }
                }
                const int sh = 8 * (j & 3);
                g[j >> 2] = (g[j >> 2] & ~(0xFFu << sh)) | ((unsigned int)h << sh);
            }
        }
    }

    uint4* out = g_h4 + (size_t)row * 64 + lane * 2;
    out[0] = make_uint4(g[0], g[1], g[2], g[3]);
    out[1] = make_uint4(g[4], g[5], g[6], g[7]);
}

// ---------------------------------------------------------------------------
// Kernel 2: Chebyshev DT column combine (SIMD bytes) + pack 4B fusion records.
// 8 px/thread. d(x,y) = min_r max(r, min(h[y-r], h[y+r])), early exit.
// ---------------------------------------------------------------------------
__device__ __forceinline__ unsigned int hmax8(unsigned int a, unsigned int b) {
    unsigned int m = __vmaxu4(a, b);
    m = __vmaxu4(m, m >> 16);
    m = __vmaxu4(m, m >> 8);
    return m & 0xFFu;
}

__device__ __forceinline__ unsigned int make_rec(unsigned int dbits, unsigned int ebits,
                                                 unsigned int b8) {
    // code = floor((d+2)/3) in 0..16 (exact via *171>>9 for d<=46); edge bit from f32 0/1
    const unsigned int c = ((b8 + 2u) * 171u) >> 9;
    return ((dbits + 32u) & ~63u) | (c << 1) | ((ebits >> 29) & 1u);
}

__global__ void col_pack_kernel(const uint4* __restrict__ depth4,
                                const uint4* __restrict__ edge4) {
    const int tid = blockIdx.x * blockDim.x + threadIdx.x;   // 0 .. NPIX/8-1
    const int y = (tid >> 7) & (IMH - 1);
    const unsigned long long* gh = (const unsigned long long*)g_h4;
    const size_t cbase = ((size_t)(tid >> 17) << 17) + (tid & 127); // b*131072 + x8

    const unsigned long long hv = gh[tid];
    unsigned int blo = (unsigned int)hv, bhi = (unsigned int)(hv >> 32);
    unsigned int bmax = hmax8(blo, bhi);

    #pragma unroll 1
    for (unsigned int r = 1; r < bmax; ++r) {
        const int yu = y - (int)r;
        const int yd = y + (int)r;
        unsigned int ulo = 0x2E2E2E2Eu, uhi = 0x2E2E2E2Eu;   // DCAP bytes
        if (yu >= 0) {
            const unsigned long long hu = gh[cbase + (size_t)yu * 128];
            ulo = (unsigned int)hu; uhi = (unsigned int)(hu >> 32);
        }
        if (yd < IMH) {
            const unsigned long long hd = gh[cbase + (size_t)yd * 128];
            ulo = __vminu4(ulo, (unsigned int)hd);
            uhi = __vminu4(uhi, (unsigned int)(hd >> 32));
        }
        const unsigned int rq = r * 0x01010101u;
        blo = __vminu4(blo, __vmaxu4(ulo, rq));
        bhi = __vminu4(bhi, __vmaxu4(uhi, rq));
        bmax = hmax8(blo, bhi);
    }

    const uint4 d0 = depth4[tid * 2], d1 = depth4[tid * 2 + 1];
    const uint4 e0 = edge4[tid * 2],  e1 = edge4[tid * 2 + 1];

    uint4 pA, pB;
    pA.x = make_rec(d0.x, e0.x,  blo        & 0xFFu);
    pA.y = make_rec(d0.y, e0.y, (blo >>  8) & 0xFFu);
    pA.z = make_rec(d0.z, e0.z, (blo >> 16) & 0xFFu);
    pA.w = make_rec(d0.w, e0.w,  blo >> 24);
    pB.x = make_rec(d1.x, e1.x,  bhi        & 0xFFu);
    pB.y = make_rec(d1.y, e1.y, (bhi >>  8) & 0xFFu);
    pB.z = make_rec(d1.z, e1.z, (bhi >> 16) & 0xFFu);
    pB.w = make_rec(d1.w, e1.w,  bhi >> 24);
    g_p4[tid * 2]     = pA;
    g_p4[tid * 2 + 1] = pB;
}

// ---------------------------------------------------------------------------
// Kernel 3: fused bilinear sampling + psdf weighting + occupancy fusion.
// 4 queries/thread (float4 I/O, 16 outstanding 4B gathers into 16MB L2 image).
// ---------------------------------------------------------------------------
__device__ __forceinline__ float fuse_one(int b, float px, float py, float zz,
                                          float ob, float of) {
    const unsigned int* __restrict__ gp = (const unsigned int*)g_p4;

    const float gx = (px + 1.0f) * 0.5f * (float)(IMW - 1);
    const float gy = (py + 1.0f) * 0.5f * (float)(IMH - 1);
    const float x0f = floorf(gx);
    const float y0f = floorf(gy);
    const float wx = gx - x0f;
    const float wy = gy - y0f;

    const int x0 = (int)fminf(fmaxf(x0f,        0.0f), (float)(IMW - 1));
    const int x1 = (int)fminf(fmaxf(x0f + 1.0f, 0.0f), (float)(IMW - 1));
    const int y0 = (int)fminf(fmaxf(y0f,        0.0f), (float)(IMH - 1));
    const int y1 = (int)fminf(fmaxf(y0f + 1.0f, 0.0f), (float)(IMH - 1));

    const size_t base = (size_t)b * IMH * IMW;
    const unsigned int u00 = __ldg(&gp[base + (size_t)y0 * IMW + x0]);
    const unsigned int u10 = __ldg(&gp[base + (size_t)y0 * IMW + x1]);
    const unsigned int u01 = __ldg(&gp[base + (size_t)y1 * IMW + x0]);
    const unsigned int u11 = __ldg(&gp[base + (size_t)y1 * IMW + x1]);

    const float w00 = (1.0f - wx) * (1.0f - wy);
    const float w10 = wx * (1.0f - wy);
    const float w01 = (1.0f - wx) * wy;
    const float w11 = wx * wy;

    const float edge = (float)(u00 & 1u) * w00 + (float)(u10 & 1u) * w10
                     + (float)(u01 & 1u) * w01 + (float)(u11 & 1u) * w11;

    const float dq = __uint_as_float(u00 & ~63u) * w00 + __uint_as_float(u10 & ~63u) * w10
                   + __uint_as_float(u01 & ~63u) * w01 + __uint_as_float(u11 & ~63u) * w11;

    const int c00 = (int)((u00 >> 1) & 31u), c10 = (int)((u10 >> 1) & 31u);
    const int c01 = (int)((u01 >> 1) & 31u), c11 = (int)((u11 >> 1) & 31u);
    const float v00 = c00 ? (0.1f + 0.06f * (float)(c00 - 1)) : 0.0f;
    const float v10 = c10 ? (0.1f + 0.06f * (float)(c10 - 1)) : 0.0f;
    const float v01 = c01 ? (0.1f + 0.06f * (float)(c01 - 1)) : 0.0f;
    const float v11 = c11 ? (0.1f + 0.06f * (float)(c11 - 1)) : 0.0f;
    const float lab = v00 * w00 + v10 * w10 + v01 * w01 + v11 * w11;

    const float eb = (edge > 0.01f) ? 1.0f : 0.0f;
    const float psdf = zz - dq * eb;
    const float w = expf(-psdf * psdf * 1000.0f) * lab * eb;
    return w * of + (1.0f - w) * ob;
}

__global__ void fuse_kernel(const float* __restrict__ xy,
                            const float* __restrict__ z,
                            const float* __restrict__ occ_body,
                            const float* __restrict__ occ_face,
                            float* __restrict__ out) {
    const int t = blockIdx.x * blockDim.x + threadIdx.x;     // 0 .. NB*NQ/4-1
    const int i0 = t * 4;
    const int b = i0 >> 18;
    const int n0 = i0 & (NQ - 1);

    const float4 xs = *(const float4*)(xy + (size_t)b * 2 * NQ + n0);
    const float4 ys = *(const float4*)(xy + (size_t)b * 2 * NQ + NQ + n0);
    const float4 zs  = *(const float4*)(z + i0);
    const float4 obs = *(const float4*)(occ_body + i0);
    const float4 ofs = *(const float4*)(occ_face + i0);

    float4 r;
    r.x = fuse_one(b, xs.x, ys.x, zs.x, obs.x, ofs.x);
    r.y = fuse_one(b, xs.y, ys.y, zs.y, obs.y, ofs.y);
    r.z = fuse_one(b, xs.z, ys.z, zs.z, obs.z, ofs.z);
    r.w = fuse_one(b, xs.w, ys.w, zs.w, obs.w, ofs.w);
    *(float4*)(out + i0) = r;
}

// ---------------------------------------------------------------------------
extern "C" void kernel_launch(void* const* d_in, const int* in_sizes, int n_in,
                              void* d_out, int out_size) {
    const float* mask       = (const float*)d_in[0];
    const float* face_depth = (const float*)d_in[1];
    const float* edge_mask  = (const float*)d_in[2];
    const float* xy         = (const float*)d_in[3];
    const float* z          = (const float*)d_in[4];
    const float* occ_body   = (const float*)d_in[5];
    const float* occ_face   = (const float*)d_in[6];
    float* out = (float*)d_out;

    (void)in_sizes; (void)n_in; (void)out_size;

    // 1) per-row nearest-zero distance (warp-per-row, coalesced + shfl transpose)
    row_dist_kernel<<<NB * IMH / 8, 256>>>((const uint4*)mask);
    // 2) Chebyshev DT column combine + 4B record pack (8 px/thread, SIMD bytes)
    col_pack_kernel<<<(int)(NPIX / 8 / 256), 256>>>((const uint4*)face_depth,
                                                    (const uint4*)edge_mask);
    // 3) fused sampling + fusion (4 queries/thread, 16 gathers in flight)
    fuse_kernel<<<(NB * NQ / 4) / 256, 256>>>(xy, z, occ_body, occ_face, out);
}